// round 3
// baseline (speedup 1.0000x reference)
#include <cuda_runtime.h>

typedef unsigned long long ull;

// ---------------- problem constants ----------------
constexpr int Bsz = 65536, T = 15, Hd = 128, INF = 6, OUTF = 3, HORIZON = 10;
constexpr int BT = 32;          // batch rows per block
constexpr int THREADS = 256;    // 128 hidden-units x 2 batch groups of 16

// ---------------- device-global scratch (static, no runtime alloc) ----------------
// packed gate-quad weights, transposed to [k][u] with float4 = (i,f,g,o) rows for unit u
constexpr int OFF_IH0 = 0;                   // 6*128
constexpr int OFF_HH0 = 768;                 // 128*128
constexpr int OFF_IH1 = OFF_HH0 + 16384;
constexpr int OFF_HH1 = OFF_IH1 + 16384;
constexpr int OFF_IHD = OFF_HH1 + 16384;
constexpr int OFF_HHD = OFF_IHD + 16384;
constexpr int WQ_TOTAL = OFF_HHD + 16384;

__device__ float4 g_Wq[WQ_TOTAL];
__device__ float4 g_bq[3 * 128];             // bias quads: 0..127 b0, 128..255 b1, 256..383 bd
__device__ float  g_stepbias[HORIZON * 128]; // bp + emb[s] @ Wp[:,3:].T
__device__ float  g_wpprev[3 * 128];         // Wp[:, :3] transposed -> [p][j]

// ---------------- shared-memory layout (floats) ----------------
constexpr int S_H0   = 0;                    // [128][32]
constexpr int S_H1   = 4096;                 // [128][32]
constexpr int S_A    = 8192;                 // din [j][32] (4096) OR feat [b][130] (4160)
constexpr int S_X    = S_A + 4224;           // [t][p][32] = 2880
constexpr int S_PREV = S_X + 2880;           // [3][32]
constexpr int S_MU   = S_PREV + 96;          // 32
constexpr int S_RSTD = S_MU + 32;            // 32
constexpr int S_PS   = S_RSTD + 32;          // [8][32] partial sums
constexpr int S_LNG  = S_PS + 256;           // 128
constexpr int S_LNB  = S_LNG + 128;          // 128
constexpr int S_WM   = S_LNB + 128;          // [3][128]
constexpr int S_WS   = S_WM + 384;           // [3][128]
constexpr int S_TOTAL = S_WS + 384;          // 16736 floats
constexpr int SMEM_BYTES = S_TOTAL * 4;      // 66944 B

// ---------------- f32x2 helpers ----------------
__device__ __forceinline__ void fma2(ull& a, ull b, ull c) {
    asm("fma.rn.f32x2 %0, %1, %2, %0;" : "+l"(a) : "l"(b), "l"(c));
}
__device__ __forceinline__ ull pack2(float x, float y) {
    ull r; asm("mov.b64 %0, {%1,%2};" : "=l"(r) : "f"(x), "f"(y)); return r;
}
__device__ __forceinline__ float2 unpack2(ull v) {
    float2 r; asm("mov.b64 {%0,%1}, %2;" : "=f"(r.x), "=f"(r.y) : "l"(v)); return r;
}
__device__ __forceinline__ float sigf(float x) {
    return __fdividef(1.f, 1.f + __expf(-x));
}

// accumulate gates over K input dims: S is the SMEM activation tile base,
// already offset by this thread's batch-group (bb); rows stride BT floats.
__device__ __forceinline__ void gate_accum(
    const float4* __restrict__ Wq, int K, const float* __restrict__ S, int u,
    ull ai[8], ull af[8], ull ag[8], ull ao[8])
{
    #pragma unroll 4
    for (int k = 0; k < K; k++) {
        float4 w = __ldg(&Wq[k * 128 + u]);
        ull wi = pack2(w.x, w.x), wf = pack2(w.y, w.y);
        ull wg = pack2(w.z, w.z), wo = pack2(w.w, w.w);
        const ull* row = (const ull*)(S + k * BT);
        #pragma unroll
        for (int p = 0; p < 8; p++) {
            ull v = row[p];
            fma2(ai[p], wi, v);
            fma2(af[p], wf, v);
            fma2(ag[p], wg, v);
            fma2(ao[p], wo, v);
        }
    }
}

__device__ __forceinline__ void init_acc(ull ai[8], ull af[8], ull ag[8], ull ao[8], float4 b) {
    ull bi = pack2(b.x, b.x), bf = pack2(b.y, b.y), bg = pack2(b.z, b.z), bo = pack2(b.w, b.w);
    #pragma unroll
    for (int p = 0; p < 8; p++) { ai[p] = bi; af[p] = bf; ag[p] = bg; ao[p] = bo; }
}

// apply LSTM nonlinearity, update c (regs) and write new h (SMEM row for unit u, this group)
__device__ __forceinline__ void lstm_update(
    const ull ai[8], const ull af[8], const ull ag[8], const ull ao[8],
    float c[16], float* Hrow)
{
    #pragma unroll
    for (int p = 0; p < 8; p++) {
        float2 iv = unpack2(ai[p]), fv = unpack2(af[p]);
        float2 gv = unpack2(ag[p]), ov = unpack2(ao[p]);
        float c0 = sigf(fv.x) * c[2*p]   + sigf(iv.x) * tanhf(gv.x);
        float c1 = sigf(fv.y) * c[2*p+1] + sigf(iv.y) * tanhf(gv.y);
        c[2*p] = c0; c[2*p+1] = c1;
        float h0 = sigf(ov.x) * tanhf(c0);
        float h1 = sigf(ov.y) * tanhf(c1);
        ((float2*)Hrow)[p] = make_float2(h0, h1);
    }
}

// ---------------- prep kernels ----------------
__global__ void k_pack(const float* __restrict__ W, int K, int off) {
    int idx = blockIdx.x * blockDim.x + threadIdx.x;
    if (idx >= K * 128) return;
    int k = idx >> 7, u = idx & 127;
    g_Wq[off + idx] = make_float4(W[u * K + k], W[(128 + u) * K + k],
                                  W[(256 + u) * K + k], W[(384 + u) * K + k]);
}
__global__ void k_packb(const float* __restrict__ b, int off) {
    int u = threadIdx.x;
    g_bq[off + u] = make_float4(b[u], b[128 + u], b[256 + u], b[384 + u]);
}
__global__ void k_dec_prep(const float* __restrict__ emb, const float* __restrict__ Wp,
                           const float* __restrict__ bp) {
    int j = threadIdx.x;
    if (blockIdx.x < HORIZON) {
        int s = blockIdx.x;
        float acc = bp[j];
        #pragma unroll 4
        for (int k = 0; k < Hd; k++) acc += emb[s * Hd + k] * Wp[j * (OUTF + Hd) + OUTF + k];
        g_stepbias[s * 128 + j] = acc;
    } else {
        int p = blockIdx.x - HORIZON;
        g_wpprev[p * 128 + j] = Wp[j * (OUTF + Hd) + p];
    }
}

// ---------------- main persistent kernel ----------------
__global__ __launch_bounds__(THREADS, 1)
void traj_main(const float* __restrict__ x,
               const float* __restrict__ Wm, const float* __restrict__ bm,
               const float* __restrict__ Ws, const float* __restrict__ bs,
               const float* __restrict__ lng, const float* __restrict__ lnb,
               float* __restrict__ out)
{
    extern __shared__ float sm[];
    const int tid = threadIdx.x;
    const int u = tid & 127;        // hidden unit owned by this thread
    const int bb = (tid >> 7) * 16; // batch sub-group base (0 or 16)
    const int b0g = blockIdx.x * BT;

    // ---- stage x tile, LN params, head weights; zero states ----
    for (int i = tid; i < BT * T * INF; i += THREADS) {
        int b = i / (T * INF), r = i % (T * INF);
        sm[S_X + r * BT + b] = x[(size_t)(b0g + b) * (T * INF) + r];
    }
    for (int i = tid; i < 8192; i += THREADS) sm[S_H0 + i] = 0.f;
    if (tid < 128) { sm[S_LNG + tid] = lng[tid]; sm[S_LNB + tid] = lnb[tid]; }
    for (int i = tid; i < 384; i += THREADS) { sm[S_WM + i] = Wm[i]; sm[S_WS + i] = Ws[i]; }

    // head biases hoisted out of the decoder loop
    const float bm_r = (tid < 96) ? bm[tid >> 5] : 0.f;
    const float bs_r = (tid < 96) ? bs[tid >> 5] : 0.f;

    float c0r[16], c1r[16];
    #pragma unroll
    for (int p = 0; p < 16; p++) { c0r[p] = 0.f; c1r[p] = 0.f; }
    __syncthreads();

    ull ai[8], af[8], ag[8], ao[8];

    // ---- encoder: 2 stacked LSTM layers, fused per time step ----
    for (int t = 0; t < T; t++) {
        // layer 0
        init_acc(ai, af, ag, ao, g_bq[u]);
        gate_accum(g_Wq + OFF_IH0, INF, sm + S_X + t * (INF * BT) + bb, u, ai, af, ag, ao);
        gate_accum(g_Wq + OFF_HH0, Hd,  sm + S_H0 + bb, u, ai, af, ag, ao);
        __syncthreads();
        lstm_update(ai, af, ag, ao, c0r, sm + S_H0 + u * BT + bb);
        __syncthreads();
        // layer 1 (consumes new h0)
        init_acc(ai, af, ag, ao, g_bq[128 + u]);
        gate_accum(g_Wq + OFF_IH1, Hd, sm + S_H0 + bb, u, ai, af, ag, ao);
        gate_accum(g_Wq + OFF_HH1, Hd, sm + S_H1 + bb, u, ai, af, ag, ao);
        __syncthreads();
        lstm_update(ai, af, ag, ao, c1r, sm + S_H1 + u * BT + bb);
        __syncthreads();
    }

    // ---- prev0 = x[:, T-1, :3] ----
    if (tid < BT) {
        #pragma unroll
        for (int p = 0; p < OUTF; p++)
            sm[S_PREV + p * BT + tid] = sm[S_X + ((T - 1) * INF + p) * BT + tid];
    }
    __syncthreads();

    // ---- decoder: 10 steps ----
    for (int s = 0; s < HORIZON; s++) {
        // dec_in[j] = relu(stepbias + prev @ Wp[:, :3].T)  -> sm[S_A] as [j][b]
        {
            float w0 = g_wpprev[u], w1 = g_wpprev[128 + u], w2 = g_wpprev[256 + u];
            float sb = g_stepbias[s * 128 + u];
            #pragma unroll
            for (int i = 0; i < 16; i++) {
                int b = bb + ((i + u) & 15);
                float v = sb + w0 * sm[S_PREV + b] + w1 * sm[S_PREV + BT + b]
                             + w2 * sm[S_PREV + 2 * BT + b];
                sm[S_A + u * BT + b] = fmaxf(v, 0.f);
            }
        }
        __syncthreads();

        init_acc(ai, af, ag, ao, g_bq[256 + u]);
        gate_accum(g_Wq + OFF_IHD, Hd, sm + S_A  + bb, u, ai, af, ag, ao);
        gate_accum(g_Wq + OFF_HHD, Hd, sm + S_H1 + bb, u, ai, af, ag, ao);
        __syncthreads();
        lstm_update(ai, af, ag, ao, c1r, sm + S_H1 + u * BT + bb);
        __syncthreads();

        // LayerNorm over H per batch row (warp-partial reductions, conflict-free)
        int w = tid >> 5, lane = tid & 31;
        float s1 = 0.f;
        #pragma unroll
        for (int i = 0; i < 16; i++) s1 += sm[S_H1 + (w * 16 + i) * BT + lane];
        sm[S_PS + w * 32 + lane] = s1;
        __syncthreads();
        if (tid < 32) {
            float m = 0.f;
            #pragma unroll
            for (int ww = 0; ww < 8; ww++) m += sm[S_PS + ww * 32 + tid];
            sm[S_MU + tid] = m * (1.f / 128.f);
        }
        __syncthreads();
        float mu_b = sm[S_MU + lane];
        float s2 = 0.f;
        #pragma unroll
        for (int i = 0; i < 16; i++) {
            float d = sm[S_H1 + (w * 16 + i) * BT + lane] - mu_b;
            s2 += d * d;
        }
        sm[S_PS + w * 32 + lane] = s2;
        __syncthreads();
        if (tid < 32) {
            float v = 0.f;
            #pragma unroll
            for (int ww = 0; ww < 8; ww++) v += sm[S_PS + ww * 32 + tid];
            sm[S_RSTD + tid] = rsqrtf(v * (1.f / 128.f) + 1e-5f);
        }
        __syncthreads();
        // feat -> sm[S_A] re-laid-out as [b][130]
        {
            float gg = sm[S_LNG + u], be = sm[S_LNB + u];
            #pragma unroll
            for (int i = 0; i < 16; i++) {
                int b = bb + ((i + u) & 15);
                sm[S_A + b * 130 + u] =
                    (sm[S_H1 + u * BT + b] - sm[S_MU + b]) * sm[S_RSTD + b] * gg + be;
            }
        }
        __syncthreads();

        // heads: warp per output channel o, lane per batch row b
        if (tid < 96) {
            int o = tid >> 5, b = tid & 31;
            float am = bm_r, asv = bs_r;
            #pragma unroll 4
            for (int k = 0; k < 128; k++) {
                float f = sm[S_A + b * 130 + k];
                am  += f * sm[S_WM + o * 128 + k];
                asv += f * sm[S_WS + o * 128 + k];
            }
            size_t oi = ((size_t)(b0g + b) * HORIZON + s) * OUTF + o;
            out[oi] = am;
            out[(size_t)Bsz * HORIZON * OUTF + oi] = fminf(fmaxf(asv, -6.f), 3.f);
            sm[S_PREV + o * BT + b] = am;   // prev = mu
        }
        __syncthreads();
    }
}

// ---------------- launch ----------------
extern "C" void kernel_launch(void* const* d_in, const int* in_sizes, int n_in,
                              void* d_out, int out_size)
{
    const float* x     = (const float*)d_in[0];
    const float* W_ih0 = (const float*)d_in[1];
    const float* W_hh0 = (const float*)d_in[2];
    const float* b0    = (const float*)d_in[3];
    const float* W_ih1 = (const float*)d_in[4];
    const float* W_hh1 = (const float*)d_in[5];
    const float* b1    = (const float*)d_in[6];
    const float* W_ihd = (const float*)d_in[7];
    const float* W_hhd = (const float*)d_in[8];
    const float* bd    = (const float*)d_in[9];
    const float* emb   = (const float*)d_in[10];
    const float* Wp    = (const float*)d_in[11];
    const float* bp    = (const float*)d_in[12];
    const float* Wm    = (const float*)d_in[13];
    const float* bm    = (const float*)d_in[14];
    const float* Ws    = (const float*)d_in[15];
    const float* bs    = (const float*)d_in[16];
    const float* ln_g  = (const float*)d_in[17];
    const float* ln_b  = (const float*)d_in[18];

    cudaFuncSetAttribute(traj_main, cudaFuncAttributeMaxDynamicSharedMemorySize, SMEM_BYTES);

    k_pack<<<(6 * 128 + 255) / 256, 256>>>(W_ih0, 6,  OFF_IH0);
    k_pack<<<64, 256>>>(W_hh0, 128, OFF_HH0);
    k_pack<<<64, 256>>>(W_ih1, 128, OFF_IH1);
    k_pack<<<64, 256>>>(W_hh1, 128, OFF_HH1);
    k_pack<<<64, 256>>>(W_ihd, 128, OFF_IHD);
    k_pack<<<64, 256>>>(W_hhd, 128, OFF_HHD);
    k_packb<<<1, 128>>>(b0, 0);
    k_packb<<<1, 128>>>(b1, 128);
    k_packb<<<1, 128>>>(bd, 256);
    k_dec_prep<<<HORIZON + OUTF, 128>>>(emb, Wp, bp);

    traj_main<<<Bsz / BT, THREADS, SMEM_BYTES>>>(x, Wm, bm, Ws, bs, ln_g, ln_b, (float*)d_out);
}